// round 6
// baseline (speedup 1.0000x reference)
#include <cuda_runtime.h>
#include <cuda_fp16.h>
#include <cstdint>

// ============================================================================
// Problem dims (fixed by setup_inputs)
// ============================================================================
#define DIN    2048
#define DOUT   2048
#define MROWS  8192        // B*S = 4*2048
#define GROUPS 64          // DIN/32

// ============================================================================
// Scratch (device globals; no allocation allowed)
// ============================================================================
__device__ int8_t g_xq8[(size_t)MROWS * DIN];   // int8 q (pre-zp-subtraction, exact)
__device__ int8_t g_w8[(size_t)DOUT * DIN];     // int8 w_int (exact int4 values)
__device__ float2 g_xmeta[MROWS];               // (scale, zp) per token
__device__ float  g_wsum[DOUT];                 // sum_k w_dq[o,k]

// ============================================================================
// PTX helpers (sm_80-level portable: cp.async, ldmatrix, mma.sync)
// ============================================================================
__device__ __forceinline__ uint32_t smem_to_u32(const void* smem_ptr) {
    uint32_t addr;
    asm("{ .reg .u64 tmp; cvta.to.shared.u64 tmp, %1; cvt.u32.u64 %0, tmp; }"
        : "=r"(addr) : "l"(smem_ptr));
    return addr;
}

__device__ __forceinline__ void cp_async16(uint32_t smem_addr, const void* gptr) {
    asm volatile("cp.async.cg.shared.global [%0], [%1], 16;"
                 :: "r"(smem_addr), "l"(gptr));
}

template <int N>
__device__ __forceinline__ void cp_wait() {
    asm volatile("cp.async.wait_group %0;" :: "n"(N) : "memory");
}

__device__ __forceinline__ void ldsm_x4(uint32_t* r, uint32_t addr) {
    asm volatile("ldmatrix.sync.aligned.m8n8.x4.shared.b16 {%0,%1,%2,%3}, [%4];"
                 : "=r"(r[0]), "=r"(r[1]), "=r"(r[2]), "=r"(r[3])
                 : "r"(addr));
}

// int8 mma: D(s32) = A(s8,m16k32) * B(s8,n8k32), C = 0
__device__ __forceinline__ void imma16832(int* d, const uint32_t* a,
                                          uint32_t b0, uint32_t b1) {
    asm volatile(
        "mma.sync.aligned.m16n8k32.row.col.s32.s8.s8.s32 "
        "{%0,%1,%2,%3}, {%4,%5,%6,%7}, {%8,%9}, {%10,%10,%10,%10};"
        : "=r"(d[0]), "=r"(d[1]), "=r"(d[2]), "=r"(d[3])
        : "r"(a[0]), "r"(a[1]), "r"(a[2]), "r"(a[3]),
          "r"(b0), "r"(b1), "r"(0));
}

// Exact int32 -> float for |v| < 2^22 (IADD3 + FADD, both exact)
__device__ __forceinline__ float i2f_exact(int v) {
    return __int_as_float(0x4B400000 + v) - 12582912.0f;
}

// ============================================================================
// Kernel 1: per-token asymmetric int8 quant of x (exact jnp replication)
// Stores q (int8), and (scale, zp) per row.
// ============================================================================
__device__ __forceinline__ int q_elem(float xv, float scale, float zpf) {
    float q = rintf(__fdiv_rn(xv, scale)) + zpf;   // round-half-even like jnp.round
    q = fminf(fmaxf(q, -128.0f), 127.0f);
    return (int)q;   // exact integer in [-128, 127]
}

__global__ void __launch_bounds__(256)
quant_x_kernel(const float* __restrict__ x) {
    __shared__ float red[18];
    const int row = blockIdx.x;
    const int tid = threadIdx.x;
    const float4* xr = (const float4*)(x + (size_t)row * DIN);
    float4 v0 = xr[tid];
    float4 v1 = xr[tid + 256];

    float mn = 0.0f, mx = 0.0f;   // reference min/max include 0
    mn = fminf(mn, fminf(fminf(v0.x, v0.y), fminf(v0.z, v0.w)));
    mn = fminf(mn, fminf(fminf(v1.x, v1.y), fminf(v1.z, v1.w)));
    mx = fmaxf(mx, fmaxf(fmaxf(v0.x, v0.y), fmaxf(v0.z, v0.w)));
    mx = fmaxf(mx, fmaxf(fmaxf(v1.x, v1.y), fmaxf(v1.z, v1.w)));

    #pragma unroll
    for (int off = 16; off > 0; off >>= 1) {
        mn = fminf(mn, __shfl_xor_sync(0xffffffffu, mn, off));
        mx = fmaxf(mx, __shfl_xor_sync(0xffffffffu, mx, off));
    }
    if ((tid & 31) == 0) { red[tid >> 5] = mn; red[8 + (tid >> 5)] = mx; }
    __syncthreads();
    if (tid == 0) {
        float m1 = red[0], m2 = red[8];
        #pragma unroll
        for (int w = 1; w < 8; w++) {
            m1 = fminf(m1, red[w]);
            m2 = fmaxf(m2, red[8 + w]);
        }
        float scale = fmaxf(__fdiv_rn(m2 - m1, 255.0f), 1.1920929e-07f);
        float zpf = -128.0f - rintf(__fdiv_rn(m1, scale));
        zpf = fminf(fmaxf(zpf, -128.0f), 127.0f);
        red[16] = scale;
        red[17] = zpf;
        g_xmeta[row] = make_float2(scale, zpf);
    }
    __syncthreads();
    const float scale = red[16];
    const float zpf   = red[17];

    uint32_t* q32 = (uint32_t*)(g_xq8 + (size_t)row * DIN);
    uint32_t p0 = (uint32_t)(q_elem(v0.x, scale, zpf) & 0xff)
                | ((uint32_t)(q_elem(v0.y, scale, zpf) & 0xff) << 8)
                | ((uint32_t)(q_elem(v0.z, scale, zpf) & 0xff) << 16)
                | ((uint32_t)(q_elem(v0.w, scale, zpf) & 0xff) << 24);
    uint32_t p1 = (uint32_t)(q_elem(v1.x, scale, zpf) & 0xff)
                | ((uint32_t)(q_elem(v1.y, scale, zpf) & 0xff) << 8)
                | ((uint32_t)(q_elem(v1.z, scale, zpf) & 0xff) << 16)
                | ((uint32_t)(q_elem(v1.w, scale, zpf) & 0xff) << 24);
    q32[tid]       = p0;
    q32[tid + 256] = p1;
}

// ============================================================================
// Kernel 2: pack W to int8 + compute wsum[o] = sum_k w_dq[o,k]
// One warp per output row o. 256 threads = 8 warps per block.
// ============================================================================
__global__ void __launch_bounds__(256)
prep_w_kernel(const int* __restrict__ wi,
              const float* __restrict__ ws,
              const float* __restrict__ wz) {
    const int wid  = threadIdx.x >> 5;
    const int lane = threadIdx.x & 31;
    const int o    = blockIdx.x * 8 + wid;

    const int4* wrow = (const int4*)(wi + (size_t)o * DIN);
    uint32_t*   drow = (uint32_t*)(g_w8 + (size_t)o * DIN);

    float wacc = 0.0f;
    #pragma unroll
    for (int step = 0; step < 16; step++) {
        int4 w4 = wrow[step * 32 + lane];
        drow[step * 32 + lane] = (uint32_t)(w4.x & 0xff)
                               | ((uint32_t)(w4.y & 0xff) << 8)
                               | ((uint32_t)(w4.z & 0xff) << 16)
                               | ((uint32_t)(w4.w & 0xff) << 24);
        int ls = w4.x + w4.y + w4.z + w4.w;
        // reduce within octet (8 lanes = one group of 32 elems)
        ls += __shfl_xor_sync(0xffffffffu, ls, 1);
        ls += __shfl_xor_sync(0xffffffffu, ls, 2);
        ls += __shfl_xor_sync(0xffffffffu, ls, 4);
        if ((lane & 7) == 0) {
            int g = step * 4 + (lane >> 3);
            float s = ws[o * GROUPS + g];
            float z = wz[o * GROUPS + g];
            wacc += s * ((float)ls - 32.0f * z);
        }
    }
    wacc += __shfl_xor_sync(0xffffffffu, wacc, 8);
    wacc += __shfl_xor_sync(0xffffffffu, wacc, 16);
    if (lane == 0) g_wsum[o] = wacc;
}

// ============================================================================
// Kernel 3: int8 IMMA GEMM (NT), 128x128 tile, BK=64 (2 groups/iter),
// 3-stage cp.async pipeline, per-group fp32 scaling via exact i2f.
//   out[m,n] = sx[m] * ( sum_g s[n,g]*G[m,n,g] - zp[m]*wsum[n] )
//
// SMEM int8 rows: 64 data + 16 pad = 80B stride (ldmatrix phases conflict-free)
// ============================================================================
static constexpr int BM = 128;
static constexpr int BN = 128;
static constexpr int BK = 64;                 // int8 k per stage (2 groups)
static constexpr int KITERS = DIN / BK;       // 32
static constexpr int SROWB = 80;              // bytes per smem row
static constexpr int TILE_B = 128 * SROWB;    // 10240 per operand per stage
static constexpr int A_OFF = 0;
static constexpr int B_OFF = 3 * TILE_B;                 // 30720
static constexpr int S_OFF = 6 * TILE_B;                 // 61440 (scale slab)
static constexpr int GEMM_SMEM = S_OFF + GROUPS * BN * 4;  // 61440+32768 = 94208

__global__ void __launch_bounds__(256, 2)
qgemm_kernel(const float* __restrict__ ws, float* __restrict__ out) {
    extern __shared__ char sm[];
    const uint32_t sbase = smem_to_u32(sm);
    const int tid  = threadIdx.x;
    const int lane = tid & 31;
    const int wid  = tid >> 5;
    const int warp_m = wid & 3;    // 4 m-tiles of 32 rows
    const int warp_n = wid >> 2;   // 2 n-tiles of 64 cols
    const int n0 = blockIdx.x * BN;
    const int m0 = blockIdx.y * BM;

    const int8_t* ga = g_xq8 + (size_t)m0 * DIN;
    const int8_t* gb = g_w8  + (size_t)n0 * DIN;

    // Stage the CTA's scale slab: s_sm[g][n_local] fp32, coalesced LDG.
    for (int idx = tid; idx < GROUPS * BN; idx += 256) {
        int o = idx >> 6;          // 0..127 (n_local)
        int g = idx & 63;
        *(float*)(sm + S_OFF + (g * BN + o) * 4) = ws[(size_t)(n0 + o) * GROUPS + g];
    }

    const int r0 = tid >> 2;             // 0..63
    const int ch = (tid & 3) * 16;       // byte chunk in row

    auto load_stage = [&](int s, int k0) {
        const uint32_t sa = sbase + A_OFF + (uint32_t)s * TILE_B;
        const uint32_t sb = sbase + B_OFF + (uint32_t)s * TILE_B;
        cp_async16(sa + (uint32_t)r0 * SROWB + ch,        ga + (size_t)r0 * DIN + k0 + ch);
        cp_async16(sa + (uint32_t)(r0 + 64) * SROWB + ch, ga + (size_t)(r0 + 64) * DIN + k0 + ch);
        cp_async16(sb + (uint32_t)r0 * SROWB + ch,        gb + (size_t)r0 * DIN + k0 + ch);
        cp_async16(sb + (uint32_t)(r0 + 64) * SROWB + ch, gb + (size_t)(r0 + 64) * DIN + k0 + ch);
        asm volatile("cp.async.commit_group;" ::: "memory");
    };

    float acc[2][8][4];
    #pragma unroll
    for (int mi = 0; mi < 2; mi++)
        #pragma unroll
        for (int p = 0; p < 8; p++)
            #pragma unroll
            for (int j = 0; j < 4; j++)
                acc[mi][p][j] = 0.0f;

    load_stage(0, 0);
    load_stage(1, BK);

    // ldmatrix lane addressing: lanes 0-15 -> rows, lanes 16-31 -> rows at +16B
    const uint32_t lrow = (uint32_t)(lane & 15);
    const uint32_t lkof = (uint32_t)((lane >> 4) * 16);

    int sc = 0;
    for (int i = 0; i < KITERS; i++) {
        if (i + 1 < KITERS) cp_wait<1>(); else cp_wait<0>();
        __syncthreads();
        if (i + 2 < KITERS) {
            int sl = sc + 2; if (sl >= 3) sl -= 3;
            load_stage(sl, (i + 2) * BK);
        }

        const uint32_t sa = sbase + A_OFF + (uint32_t)sc * TILE_B;
        const uint32_t sb = sbase + B_OFF + (uint32_t)sc * TILE_B;

        #pragma unroll
        for (int ka = 0; ka < 2; ka++) {
            const uint32_t kb = (uint32_t)(ka * 32) + lkof;
            const int g = i * 2 + ka;

            uint32_t a[2][4];
            ldsm_x4(a[0], sa + (uint32_t)(warp_m * 32 +      lrow) * SROWB + kb);
            ldsm_x4(a[1], sa + (uint32_t)(warp_m * 32 + 16 + lrow) * SROWB + kb);

            uint32_t bq[4][4];
            #pragma unroll
            for (int t = 0; t < 4; t++)
                ldsm_x4(bq[t], sb + (uint32_t)(warp_n * 64 + t * 16 + lrow) * SROWB + kb);

            const char* srow = sm + S_OFF + (g * BN + warp_n * 64 + 2 * (lane & 3)) * 4;
            #pragma unroll
            for (int p = 0; p < 8; p++) {
                // x4 B load t covers ntiles 2t (regs 0,2) and 2t+1 (regs 1,3)
                uint32_t b0 = (p & 1) ? bq[p >> 1][1] : bq[p >> 1][0];
                uint32_t b1 = (p & 1) ? bq[p >> 1][3] : bq[p >> 1][2];
                float2 s2 = *(const float2*)(srow + p * 32);
                #pragma unroll
                for (int mi = 0; mi < 2; mi++) {
                    int d[4];
                    imma16832(d, a[mi], b0, b1);
                    acc[mi][p][0] = fmaf(s2.x, i2f_exact(d[0]), acc[mi][p][0]);
                    acc[mi][p][1] = fmaf(s2.y, i2f_exact(d[1]), acc[mi][p][1]);
                    acc[mi][p][2] = fmaf(s2.x, i2f_exact(d[2]), acc[mi][p][2]);
                    acc[mi][p][3] = fmaf(s2.y, i2f_exact(d[3]), acc[mi][p][3]);
                }
            }
        }
        sc++; if (sc == 3) sc = 0;
    }

    // Epilogue: out = sx * (acc - zp * wsum[n])
    const int qrow = lane >> 2;          // 0..7
    const int qcol = (lane & 3) * 2;     // 0,2,4,6
    float2 wsn[8];
    #pragma unroll
    for (int p = 0; p < 8; p++)
        wsn[p] = *(const float2*)&g_wsum[n0 + warp_n * 64 + p * 8 + qcol];

    #pragma unroll
    for (int mi = 0; mi < 2; mi++) {
        const int mrow0 = m0 + warp_m * 32 + mi * 16 + qrow;
        const float2 meta0 = g_xmeta[mrow0];
        const float2 meta1 = g_xmeta[mrow0 + 8];
        float* o0 = out + (size_t)mrow0 * DOUT + n0 + warp_n * 64 + qcol;
        float* o1 = o0 + (size_t)8 * DOUT;
        #pragma unroll
        for (int p = 0; p < 8; p++) {
            *(float2*)(o0 + p * 8) = make_float2(
                meta0.x * (acc[mi][p][0] - meta0.y * wsn[p].x),
                meta0.x * (acc[mi][p][1] - meta0.y * wsn[p].y));
            *(float2*)(o1 + p * 8) = make_float2(
                meta1.x * (acc[mi][p][2] - meta1.y * wsn[p].x),
                meta1.x * (acc[mi][p][3] - meta1.y * wsn[p].y));
        }
    }
}

// ============================================================================
// Launch
// ============================================================================
extern "C" void kernel_launch(void* const* d_in, const int* in_sizes, int n_in,
                              void* d_out, int out_size) {
    (void)in_sizes; (void)n_in; (void)out_size;
    const float* x  = (const float*)d_in[0];
    const int*   wi = (const int*)d_in[1];
    const float* ws = (const float*)d_in[2];
    const float* wz = (const float*)d_in[3];
    float* out = (float*)d_out;

    cudaFuncSetAttribute(qgemm_kernel,
                         cudaFuncAttributeMaxDynamicSharedMemorySize, GEMM_SMEM);

    quant_x_kernel<<<MROWS, 256>>>(x);
    prep_w_kernel<<<DOUT / 8, 256>>>(wi, ws, wz);
    qgemm_kernel<<<dim3(DOUT / BN, MROWS / BM), 256, GEMM_SMEM>>>(ws, out);
}

// round 7
// speedup vs baseline: 1.9604x; 1.9604x over previous
#include <cuda_runtime.h>
#include <cuda_fp16.h>
#include <cstdint>

// ============================================================================
// Problem dims (fixed by setup_inputs)
// ============================================================================
#define DIN    2048
#define DOUT   2048
#define MROWS  8192        // B*S = 4*2048
#define GROUPS 64          // DIN/32

// ============================================================================
// Scratch (device globals; no allocation allowed)
// ============================================================================
__device__ __half g_xq[(size_t)MROWS * DIN];   // quantized x as exact integers in fp16
__device__ __half g_wh[(size_t)DOUT * DIN];    // dequantized weights in fp16
__device__ float  g_xscale[MROWS];             // per-token scale

// ============================================================================
// Portable PTX helpers (sm_80-level only: cp.async, ldmatrix, mma.sync)
// ============================================================================
__device__ __forceinline__ uint32_t smem_to_u32(const void* smem_ptr) {
    uint32_t addr;
    asm("{ .reg .u64 tmp; cvta.to.shared.u64 tmp, %1; cvt.u32.u64 %0, tmp; }"
        : "=r"(addr) : "l"(smem_ptr));
    return addr;
}

__device__ __forceinline__ void cp_async16(uint32_t smem_addr, const void* gptr) {
    asm volatile("cp.async.cg.shared.global [%0], [%1], 16;"
                 :: "r"(smem_addr), "l"(gptr));
}

template <int N>
__device__ __forceinline__ void cp_wait() {
    asm volatile("cp.async.wait_group %0;" :: "n"(N) : "memory");
}

__device__ __forceinline__ void ldsm_x4(uint32_t* r, uint32_t addr) {
    asm volatile("ldmatrix.sync.aligned.m8n8.x4.shared.b16 {%0,%1,%2,%3}, [%4];"
                 : "=r"(r[0]), "=r"(r[1]), "=r"(r[2]), "=r"(r[3])
                 : "r"(addr));
}

__device__ __forceinline__ void mma16816(float* d, const uint32_t* a,
                                         uint32_t b0, uint32_t b1) {
    asm volatile(
        "mma.sync.aligned.m16n8k16.row.col.f32.f16.f16.f32 "
        "{%0,%1,%2,%3}, {%4,%5,%6,%7}, {%8,%9}, {%0,%1,%2,%3};"
        : "+f"(d[0]), "+f"(d[1]), "+f"(d[2]), "+f"(d[3])
        : "r"(a[0]), "r"(a[1]), "r"(a[2]), "r"(a[3]), "r"(b0), "r"(b1));
}

// ============================================================================
// Kernel 1: per-token asymmetric int8 fake-quant of x (exact jnp replication)
// ============================================================================
__device__ __forceinline__ float qdq_elem(float xv, float scale, float zpf) {
    float q = rintf(__fdiv_rn(xv, scale)) + zpf;   // round-half-even like jnp.round
    q = fminf(fmaxf(q, -128.0f), 127.0f);
    return q - zpf;   // integer in [-255, 255], exact in fp16
}

__global__ void __launch_bounds__(256)
quant_x_kernel(const float* __restrict__ x) {
    __shared__ float red[18];
    const int row = blockIdx.x;
    const int tid = threadIdx.x;
    const float4* xr = (const float4*)(x + (size_t)row * DIN);
    float4 v0 = xr[tid];
    float4 v1 = xr[tid + 256];

    float mn = 0.0f, mx = 0.0f;   // reference min/max include 0
    mn = fminf(mn, fminf(fminf(v0.x, v0.y), fminf(v0.z, v0.w)));
    mn = fminf(mn, fminf(fminf(v1.x, v1.y), fminf(v1.z, v1.w)));
    mx = fmaxf(mx, fmaxf(fmaxf(v0.x, v0.y), fmaxf(v0.z, v0.w)));
    mx = fmaxf(mx, fmaxf(fmaxf(v1.x, v1.y), fmaxf(v1.z, v1.w)));

    #pragma unroll
    for (int off = 16; off > 0; off >>= 1) {
        mn = fminf(mn, __shfl_xor_sync(0xffffffffu, mn, off));
        mx = fmaxf(mx, __shfl_xor_sync(0xffffffffu, mx, off));
    }
    if ((tid & 31) == 0) { red[tid >> 5] = mn; red[8 + (tid >> 5)] = mx; }
    __syncthreads();
    if (tid == 0) {
        float m1 = red[0], m2 = red[8];
        #pragma unroll
        for (int w = 1; w < 8; w++) {
            m1 = fminf(m1, red[w]);
            m2 = fmaxf(m2, red[8 + w]);
        }
        float scale = fmaxf(__fdiv_rn(m2 - m1, 255.0f), 1.1920929e-07f);
        float zpf = -128.0f - rintf(__fdiv_rn(m1, scale));
        zpf = fminf(fmaxf(zpf, -128.0f), 127.0f);
        red[16] = scale;
        red[17] = zpf;
        g_xscale[row] = scale;
    }
    __syncthreads();
    const float scale = red[16];
    const float zpf   = red[17];

    __half2* xq2 = (__half2*)(g_xq + (size_t)row * DIN);
    xq2[2 * tid]             = __floats2half2_rn(qdq_elem(v0.x, scale, zpf), qdq_elem(v0.y, scale, zpf));
    xq2[2 * tid + 1]         = __floats2half2_rn(qdq_elem(v0.z, scale, zpf), qdq_elem(v0.w, scale, zpf));
    xq2[2 * (tid + 256)]     = __floats2half2_rn(qdq_elem(v1.x, scale, zpf), qdq_elem(v1.y, scale, zpf));
    xq2[2 * (tid + 256) + 1] = __floats2half2_rn(qdq_elem(v1.z, scale, zpf), qdq_elem(v1.w, scale, zpf));
}

// ============================================================================
// Kernel 2: grouped-int4 dequant of W into fp16
// ============================================================================
__global__ void __launch_bounds__(256)
dequant_w_kernel(const int* __restrict__ wi,
                 const float* __restrict__ ws,
                 const float* __restrict__ wz) {
    const int idx = blockIdx.x * 256 + threadIdx.x;   // one int4 vec (4 elements)
    const int4 w4 = ((const int4*)wi)[idx];
    const int base = idx << 2;
    const int o = base >> 11;                 // / DIN
    const int g = (base & (DIN - 1)) >> 5;    // group of 32
    const float s = ws[o * GROUPS + g];
    const float z = wz[o * GROUPS + g];
    __half2 h01 = __floats2half2_rn(((float)w4.x - z) * s, ((float)w4.y - z) * s);
    __half2 h23 = __floats2half2_rn(((float)w4.z - z) * s, ((float)w4.w - z) * s);
    __half2* dst = (__half2*)(g_wh + base);
    dst[0] = h01;
    dst[1] = h23;
}

// ============================================================================
// Kernel 3: fp16 mma.sync GEMM (NT), CTA tile 128x256, warp tile 64x64,
// BK=64, 3-stage cp.async pipeline, one barrier per iter.
//   out[m, n] = g_xscale[m] * sum_k g_xq[m,k] * g_wh[n,k]
//
// SMEM: padded rows, 64 fp16 data + 8 fp16 pad = 144B stride (conflict-free
// ldmatrix: 8-row groups stride 4 banks; cp.async 16B aligned).
// ============================================================================
static constexpr int BM = 128;
static constexpr int BN = 256;
static constexpr int BK = 64;
static constexpr int KITERS = DIN / BK;            // 32
static constexpr int SROWB = 144;                  // bytes per smem row (128+16)
static constexpr int A_ROWS = BM;                  // 128
static constexpr int B_ROWS = BN;                  // 256
static constexpr int STAGE_B = (A_ROWS + B_ROWS) * SROWB;   // 55296
static constexpr int NSTAGES = 3;
static constexpr int GEMM_SMEM = NSTAGES * STAGE_B;         // 165888

__global__ void __launch_bounds__(256, 1)
qgemm_kernel(float* __restrict__ out) {
    extern __shared__ char sm[];
    const uint32_t sbase = smem_to_u32(sm);
    const int tid  = threadIdx.x;
    const int lane = tid & 31;
    const int wid  = tid >> 5;
    const int warp_m = wid & 1;    // 2 m-tiles of 64 rows
    const int warp_n = wid >> 1;   // 4 n-tiles of 64 cols
    const int n0 = blockIdx.x * BN;
    const int m0 = blockIdx.y * BM;

    const __half* ga = g_xq + (size_t)m0 * DIN;
    const __half* gb = g_wh + (size_t)n0 * DIN;

    // cp.async addressing: 8 chunks of 16B per 128B row.
    // A: 128 rows * 8 = 1024 chunks (4/thread). B: 256 rows * 8 = 2048 (8/thread).
    auto load_stage = [&](int s, int k0) {
        const uint32_t abase = sbase + (uint32_t)s * STAGE_B;
        const uint32_t bbase = abase + (uint32_t)A_ROWS * SROWB;
        #pragma unroll
        for (int it = 0; it < 4; it++) {
            int c = tid + it * 256;
            int r = c >> 3;
            int colh = (c & 7) * 8;   // halves
            cp_async16(abase + (uint32_t)(r * SROWB + colh * 2),
                       ga + (size_t)r * DIN + k0 + colh);
        }
        #pragma unroll
        for (int it = 0; it < 8; it++) {
            int c = tid + it * 256;
            int r = c >> 3;
            int colh = (c & 7) * 8;
            cp_async16(bbase + (uint32_t)(r * SROWB + colh * 2),
                       gb + (size_t)r * DIN + k0 + colh);
        }
        asm volatile("cp.async.commit_group;" ::: "memory");
    };

    float acc[4][8][4];
    #pragma unroll
    for (int mi = 0; mi < 4; mi++)
        #pragma unroll
        for (int p = 0; p < 8; p++)
            #pragma unroll
            for (int j = 0; j < 4; j++)
                acc[mi][p][j] = 0.0f;

    load_stage(0, 0);
    load_stage(1, BK);

    // ldmatrix lane addressing: lanes 0-15 -> rows, lanes 16-31 -> +16B in k
    const uint32_t lrow = (uint32_t)(lane & 15);
    const uint32_t lkof = (uint32_t)((lane >> 4) * 16);   // bytes

    int sc = 0;
    for (int i = 0; i < KITERS; i++) {
        if (i + 2 < KITERS) cp_wait<1>(); else cp_wait<0>();
        __syncthreads();
        if (i + 2 < KITERS) {
            int sl = sc + 2; if (sl >= NSTAGES) sl -= NSTAGES;
            load_stage(sl, (i + 2) * BK);
        }

        const uint32_t abase = sbase + (uint32_t)sc * STAGE_B;
        const uint32_t bbase = abase + (uint32_t)A_ROWS * SROWB;
        const uint32_t arow0 = abase + (uint32_t)(warp_m * 64 + lrow) * SROWB + lkof;
        const uint32_t brow0 = bbase + (uint32_t)(warp_n * 64 + lrow) * SROWB + lkof;

        #pragma unroll
        for (int ka = 0; ka < 4; ka++) {
            const uint32_t kb = (uint32_t)(ka * 32);   // bytes: 16 halves per step

            uint32_t bq[4][4];
            #pragma unroll
            for (int t = 0; t < 4; t++)
                ldsm_x4(bq[t], brow0 + (uint32_t)(t * 16) * SROWB + kb);

            #pragma unroll
            for (int mi = 0; mi < 4; mi++) {
                uint32_t a[4];
                ldsm_x4(a, arow0 + (uint32_t)(mi * 16) * SROWB + kb);
                #pragma unroll
                for (int t = 0; t < 4; t++) {
                    // x4 B load t covers n-atoms 2t (regs 0,2) and 2t+1 (regs 1,3)
                    mma16816(acc[mi][2 * t],     a, bq[t][0], bq[t][2]);
                    mma16816(acc[mi][2 * t + 1], a, bq[t][1], bq[t][3]);
                }
            }
        }
        sc++; if (sc == NSTAGES) sc = 0;
    }

    // Epilogue: scale by per-token scale, store fp32.
    const int qrow = lane >> 2;          // 0..7
    const int qcol = (lane & 3) * 2;     // 0,2,4,6
    #pragma unroll
    for (int mi = 0; mi < 4; mi++) {
        const int mrow0 = m0 + warp_m * 64 + mi * 16 + qrow;
        const float sc0 = g_xscale[mrow0];
        const float sc1 = g_xscale[mrow0 + 8];
        float* o0 = out + (size_t)mrow0 * DOUT + n0 + warp_n * 64 + qcol;
        float* o1 = o0 + (size_t)8 * DOUT;
        #pragma unroll
        for (int p = 0; p < 8; p++) {
            *(float2*)(o0 + p * 8) = make_float2(sc0 * acc[mi][p][0],
                                                 sc0 * acc[mi][p][1]);
            *(float2*)(o1 + p * 8) = make_float2(sc1 * acc[mi][p][2],
                                                 sc1 * acc[mi][p][3]);
        }
    }
}

// ============================================================================
// Launch
// ============================================================================
extern "C" void kernel_launch(void* const* d_in, const int* in_sizes, int n_in,
                              void* d_out, int out_size) {
    (void)in_sizes; (void)n_in; (void)out_size;
    const float* x  = (const float*)d_in[0];
    const int*   wi = (const int*)d_in[1];
    const float* ws = (const float*)d_in[2];
    const float* wz = (const float*)d_in[3];
    float* out = (float*)d_out;

    cudaFuncSetAttribute(qgemm_kernel,
                         cudaFuncAttributeMaxDynamicSharedMemorySize, GEMM_SMEM);

    quant_x_kernel<<<MROWS, 256>>>(x);
    dequant_w_kernel<<<(DOUT * DIN) / 1024, 256>>>(wi, ws, wz);
    qgemm_kernel<<<dim3(DOUT / BN, MROWS / BM), 256, GEMM_SMEM>>>(out);
}

// round 9
// speedup vs baseline: 2.3112x; 1.1789x over previous
#include <cuda_runtime.h>
#include <cuda_fp16.h>
#include <cstdint>

// ============================================================================
// Problem dims (fixed by setup_inputs)
// ============================================================================
#define DIN    2048
#define DOUT   2048
#define MROWS  8192        // B*S = 4*2048
#define GROUPS 64          // DIN/32

// ============================================================================
// Scratch (device globals; no allocation allowed)
// ============================================================================
__device__ __half g_xq[(size_t)MROWS * DIN];   // quantized x as exact integers in fp16
__device__ __half g_wh[(size_t)DOUT * DIN];    // dequantized weights in fp16
__device__ float  g_xscale[MROWS];             // per-token scale

// ============================================================================
// Portable PTX helpers (sm_80-level only: cp.async, ldmatrix, mma.sync)
// ============================================================================
__device__ __forceinline__ uint32_t smem_to_u32(const void* smem_ptr) {
    uint32_t addr;
    asm("{ .reg .u64 tmp; cvta.to.shared.u64 tmp, %1; cvt.u32.u64 %0, tmp; }"
        : "=r"(addr) : "l"(smem_ptr));
    return addr;
}

__device__ __forceinline__ void cp_async16(uint32_t smem_addr, const void* gptr) {
    asm volatile("cp.async.cg.shared.global [%0], [%1], 16;"
                 :: "r"(smem_addr), "l"(gptr));
}

template <int N>
__device__ __forceinline__ void cp_wait() {
    asm volatile("cp.async.wait_group %0;" :: "n"(N) : "memory");
}

__device__ __forceinline__ void ldsm_x4(uint32_t* r, uint32_t addr) {
    asm volatile("ldmatrix.sync.aligned.m8n8.x4.shared.b16 {%0,%1,%2,%3}, [%4];"
                 : "=r"(r[0]), "=r"(r[1]), "=r"(r[2]), "=r"(r[3])
                 : "r"(addr));
}

__device__ __forceinline__ void mma16816(float* d, const uint32_t* a,
                                         uint32_t b0, uint32_t b1) {
    asm volatile(
        "mma.sync.aligned.m16n8k16.row.col.f32.f16.f16.f32 "
        "{%0,%1,%2,%3}, {%4,%5,%6,%7}, {%8,%9}, {%0,%1,%2,%3};"
        : "+f"(d[0]), "+f"(d[1]), "+f"(d[2]), "+f"(d[3])
        : "r"(a[0]), "r"(a[1]), "r"(a[2]), "r"(a[3]), "r"(b0), "r"(b1));
}

// ============================================================================
// Kernel 1 (merged prep): blocks [0, MROWS) quantize x rows; blocks
// [MROWS, MROWS+4096) dequantize W chunks. Overlaps the two independent
// phases in one launch.
// ============================================================================
__global__ void __launch_bounds__(256)
prep_kernel(const float* __restrict__ x,
            const int* __restrict__ wi,
            const float* __restrict__ ws,
            const float* __restrict__ wz) {
    __shared__ float red[18];
    const int tid = threadIdx.x;

    if (blockIdx.x < MROWS) {
        // ---- per-token asymmetric int8 fake-quant of x ----
        const int row = blockIdx.x;
        const float4* xr = (const float4*)(x + (size_t)row * DIN);
        float4 v0 = xr[tid];
        float4 v1 = xr[tid + 256];

        float mn = 0.0f, mx = 0.0f;   // reference min/max include 0
        mn = fminf(mn, fminf(fminf(v0.x, v0.y), fminf(v0.z, v0.w)));
        mn = fminf(mn, fminf(fminf(v1.x, v1.y), fminf(v1.z, v1.w)));
        mx = fmaxf(mx, fmaxf(fmaxf(v0.x, v0.y), fmaxf(v0.z, v0.w)));
        mx = fmaxf(mx, fmaxf(fmaxf(v1.x, v1.y), fmaxf(v1.z, v1.w)));

        #pragma unroll
        for (int off = 16; off > 0; off >>= 1) {
            mn = fminf(mn, __shfl_xor_sync(0xffffffffu, mn, off));
            mx = fmaxf(mx, __shfl_xor_sync(0xffffffffu, mx, off));
        }
        if ((tid & 31) == 0) { red[tid >> 5] = mn; red[8 + (tid >> 5)] = mx; }
        __syncthreads();
        if (tid == 0) {
            float m1 = red[0], m2 = red[8];
            #pragma unroll
            for (int w = 1; w < 8; w++) {
                m1 = fminf(m1, red[w]);
                m2 = fmaxf(m2, red[8 + w]);
            }
            float scale = fmaxf(__fdiv_rn(m2 - m1, 255.0f), 1.1920929e-07f);
            float zpf = -128.0f - rintf(__fdiv_rn(m1, scale));
            zpf = fminf(fmaxf(zpf, -128.0f), 127.0f);
            red[16] = __frcp_rn(scale);   // per-element uses reciprocal-mul
            red[17] = zpf;
            g_xscale[row] = scale;
        }
        __syncthreads();
        const float rs  = red[16];
        const float zpf = red[17];

        // q = clip(rint(x/s) + zp) - zp : integer in [-255,255], exact in fp16
        auto qd = [&](float xv) -> float {
            float q = rintf(xv * rs) + zpf;
            q = fminf(fmaxf(q, -128.0f), 127.0f);
            return q - zpf;
        };

        __half2* xq2 = (__half2*)(g_xq + (size_t)row * DIN);
        xq2[2 * tid]             = __floats2half2_rn(qd(v0.x), qd(v0.y));
        xq2[2 * tid + 1]         = __floats2half2_rn(qd(v0.z), qd(v0.w));
        xq2[2 * (tid + 256)]     = __floats2half2_rn(qd(v1.x), qd(v1.y));
        xq2[2 * (tid + 256) + 1] = __floats2half2_rn(qd(v1.z), qd(v1.w));
    } else {
        // ---- grouped-int4 dequant of W into fp16 ----
        const int idx = (blockIdx.x - MROWS) * 256 + tid;   // one int4 vec
        const int4 w4 = ((const int4*)wi)[idx];
        const int base = idx << 2;
        const int o = base >> 11;                 // / DIN
        const int g = (base & (DIN - 1)) >> 5;    // group of 32
        const float s = ws[o * GROUPS + g];
        const float z = wz[o * GROUPS + g];
        __half2 h01 = __floats2half2_rn(((float)w4.x - z) * s, ((float)w4.y - z) * s);
        __half2 h23 = __floats2half2_rn(((float)w4.z - z) * s, ((float)w4.w - z) * s);
        __half2* dst = (__half2*)(g_wh + base);
        dst[0] = h01;
        dst[1] = h23;
    }
}

// ============================================================================
// Kernel 2: fp16 mma.sync GEMM (NT), CTA 128x128, warp tile 32x64, BK=64,
// 3-stage cp.async pipeline (prefetch distance 2), one barrier per iter,
// 2 CTAs/SM.
//   out[m, n] = g_xscale[m] * sum_k g_xq[m,k] * g_wh[n,k]
//
// SMEM rows: 64 fp16 data + 8 fp16 pad = 144B stride (conflict-free ldmatrix;
// 16B-aligned cp.async chunks).
// ============================================================================
static constexpr int BM = 128;
static constexpr int BN = 128;
static constexpr int BK = 64;
static constexpr int KITERS = DIN / BK;            // 32
static constexpr int SROWB = 144;                  // bytes per smem row
static constexpr int TILE_B = 128 * SROWB;         // 18432 per operand
static constexpr int STAGE_B = 2 * TILE_B;         // 36864 (A + B)
static constexpr int NSTAGES = 3;
static constexpr int GEMM_SMEM = NSTAGES * STAGE_B;  // 110592; x2 CTAs = 221KB

__global__ void __launch_bounds__(256, 2)
qgemm_kernel(float* __restrict__ out) {
    extern __shared__ char sm[];
    const uint32_t sbase = smem_to_u32(sm);
    const int tid  = threadIdx.x;
    const int lane = tid & 31;
    const int wid  = tid >> 5;
    const int warp_m = wid & 3;    // 4 m-tiles of 32 rows
    const int warp_n = wid >> 2;   // 2 n-tiles of 64 cols
    const int n0 = blockIdx.x * BN;
    const int m0 = blockIdx.y * BM;

    const __half* ga = g_xq + (size_t)m0 * DIN;
    const __half* gb = g_wh + (size_t)n0 * DIN;

    auto load_stage = [&](int s, int k0) {
        const uint32_t abase = sbase + (uint32_t)s * STAGE_B;
        const uint32_t bbase = abase + (uint32_t)TILE_B;
        #pragma unroll
        for (int it = 0; it < 4; it++) {
            int c = tid + it * 256;          // 0..1023, one 16B chunk each
            int r = c >> 3;                  // row 0..127
            int colh = (c & 7) * 8;          // column in halves
            uint32_t soff = (uint32_t)(r * SROWB + colh * 2);
            cp_async16(abase + soff, ga + (size_t)r * DIN + k0 + colh);
            cp_async16(bbase + soff, gb + (size_t)r * DIN + k0 + colh);
        }
        asm volatile("cp.async.commit_group;" ::: "memory");
    };

    float acc[2][8][4];
    #pragma unroll
    for (int mi = 0; mi < 2; mi++)
        #pragma unroll
        for (int p = 0; p < 8; p++)
            #pragma unroll
            for (int j = 0; j < 4; j++)
                acc[mi][p][j] = 0.0f;

    load_stage(0, 0);
    load_stage(1, BK);

    // ldmatrix lane addressing: lanes 0-15 -> rows, lanes 16-31 -> +16B in k
    const uint32_t lrow = (uint32_t)(lane & 15);
    const uint32_t lkof = (uint32_t)((lane >> 4) * 16);   // bytes

    int sc = 0;
    for (int i = 0; i < KITERS; i++) {
        if (i + 2 < KITERS) cp_wait<1>(); else cp_wait<0>();
        __syncthreads();
        if (i + 2 < KITERS) {
            int sl = sc + 2; if (sl >= NSTAGES) sl -= NSTAGES;
            load_stage(sl, (i + 2) * BK);
        }

        const uint32_t abase = sbase + (uint32_t)sc * STAGE_B;
        const uint32_t bbase = abase + (uint32_t)TILE_B;
        const uint32_t arow0 = abase + (uint32_t)(warp_m * 32 + lrow) * SROWB + lkof;
        const uint32_t brow0 = bbase + (uint32_t)(warp_n * 64 + lrow) * SROWB + lkof;

        #pragma unroll
        for (int ka = 0; ka < 4; ka++) {
            const uint32_t kb = (uint32_t)(ka * 32);   // 16 halves per k-step

            uint32_t a[2][4];
            ldsm_x4(a[0], arow0 + kb);
            ldsm_x4(a[1], arow0 + 16u * SROWB + kb);

            uint32_t bq[4][4];
            #pragma unroll
            for (int t = 0; t < 4; t++)
                ldsm_x4(bq[t], brow0 + (uint32_t)(t * 16) * SROWB + kb);

            #pragma unroll
            for (int mi = 0; mi < 2; mi++) {
                #pragma unroll
                for (int t = 0; t < 4; t++) {
                    // x4 B load t covers n-atoms 2t (regs 0,2) and 2t+1 (1,3)
                    mma16816(acc[mi][2 * t],     a[mi], bq[t][0], bq[t][2]);
                    mma16816(acc[mi][2 * t + 1], a[mi], bq[t][1], bq[t][3]);
                }
            }
        }
        sc++; if (sc == NSTAGES) sc = 0;
    }

    // Epilogue: scale by per-token scale, store fp32.
    const int qrow = lane >> 2;          // 0..7
    const int qcol = (lane & 3) * 2;     // 0,2,4,6
    #pragma unroll
    for (int mi = 0; mi < 2; mi++) {
        const int mrow0 = m0 + warp_m * 32 + mi * 16 + qrow;
        const float sc0 = g_xscale[mrow0];
        const float sc1 = g_xscale[mrow0 + 8];
        float* o0 = out + (size_t)mrow0 * DOUT + n0 + warp_n * 64 + qcol;
        float* o1 = o0 + (size_t)8 * DOUT;
        #pragma unroll
        for (int p = 0; p < 8; p++) {
            *(float2*)(o0 + p * 8) = make_float2(sc0 * acc[mi][p][0],
                                                 sc0 * acc[mi][p][1]);
            *(float2*)(o1 + p * 8) = make_float2(sc1 * acc[mi][p][2],
                                                 sc1 * acc[mi][p][3]);
        }
    }
}

// ============================================================================
// Launch
// ============================================================================
extern "C" void kernel_launch(void* const* d_in, const int* in_sizes, int n_in,
                              void* d_out, int out_size) {
    (void)in_sizes; (void)n_in; (void)out_size;
    const float* x  = (const float*)d_in[0];
    const int*   wi = (const int*)d_in[1];
    const float* ws = (const float*)d_in[2];
    const float* wz = (const float*)d_in[3];
    float* out = (float*)d_out;

    cudaFuncSetAttribute(qgemm_kernel,
                         cudaFuncAttributeMaxDynamicSharedMemorySize, GEMM_SMEM);

    prep_kernel<<<MROWS + (DOUT * DIN) / 1024, 256>>>(x, wi, ws, wz);
    qgemm_kernel<<<dim3(DOUT / BN, MROWS / BM), 256, GEMM_SMEM>>>(out);
}

// round 10
// speedup vs baseline: 2.3328x; 1.0093x over previous
#include <cuda_runtime.h>
#include <cuda_fp16.h>
#include <cstdint>

// ============================================================================
// Problem dims (fixed by setup_inputs)
// ============================================================================
#define DIN    2048
#define DOUT   2048
#define MROWS  8192        // B*S = 4*2048
#define GROUPS 64          // DIN/32

// ============================================================================
// Scratch (device globals; no allocation allowed)
// ============================================================================
__device__ __half g_xq[(size_t)MROWS * DIN];   // quantized x as exact integers in fp16
__device__ __half g_wh[(size_t)DOUT * DIN];    // dequantized weights in fp16
__device__ float  g_xscale[MROWS];             // per-token scale

// ============================================================================
// Portable PTX helpers (sm_80-level only: cp.async, ldmatrix, mma.sync)
// ============================================================================
__device__ __forceinline__ uint32_t smem_to_u32(const void* smem_ptr) {
    uint32_t addr;
    asm("{ .reg .u64 tmp; cvta.to.shared.u64 tmp, %1; cvt.u32.u64 %0, tmp; }"
        : "=r"(addr) : "l"(smem_ptr));
    return addr;
}

__device__ __forceinline__ void cp_async16(uint32_t smem_addr, const void* gptr) {
    asm volatile("cp.async.cg.shared.global [%0], [%1], 16;"
                 :: "r"(smem_addr), "l"(gptr));
}

template <int N>
__device__ __forceinline__ void cp_wait() {
    asm volatile("cp.async.wait_group %0;" :: "n"(N) : "memory");
}

__device__ __forceinline__ void ldsm_x4(uint32_t* r, uint32_t addr) {
    asm volatile("ldmatrix.sync.aligned.m8n8.x4.shared.b16 {%0,%1,%2,%3}, [%4];"
                 : "=r"(r[0]), "=r"(r[1]), "=r"(r[2]), "=r"(r[3])
                 : "r"(addr));
}

__device__ __forceinline__ void mma16816(float* d, const uint32_t* a,
                                         uint32_t b0, uint32_t b1) {
    asm volatile(
        "mma.sync.aligned.m16n8k16.row.col.f32.f16.f16.f32 "
        "{%0,%1,%2,%3}, {%4,%5,%6,%7}, {%8,%9}, {%0,%1,%2,%3};"
        : "+f"(d[0]), "+f"(d[1]), "+f"(d[2]), "+f"(d[3])
        : "r"(a[0]), "r"(a[1]), "r"(a[2]), "r"(a[3]), "r"(b0), "r"(b1));
}

// ============================================================================
// Kernel 1 (merged prep): blocks [0, MROWS) quantize x rows; blocks
// [MROWS, MROWS+4096) dequantize W chunks.
// ============================================================================
__global__ void __launch_bounds__(256)
prep_kernel(const float* __restrict__ x,
            const int* __restrict__ wi,
            const float* __restrict__ ws,
            const float* __restrict__ wz) {
    __shared__ float red[18];
    const int tid = threadIdx.x;

    if (blockIdx.x < MROWS) {
        // ---- per-token asymmetric int8 fake-quant of x ----
        const int row = blockIdx.x;
        const float4* xr = (const float4*)(x + (size_t)row * DIN);
        float4 v0 = xr[tid];
        float4 v1 = xr[tid + 256];

        float mn = 0.0f, mx = 0.0f;   // reference min/max include 0
        mn = fminf(mn, fminf(fminf(v0.x, v0.y), fminf(v0.z, v0.w)));
        mn = fminf(mn, fminf(fminf(v1.x, v1.y), fminf(v1.z, v1.w)));
        mx = fmaxf(mx, fmaxf(fmaxf(v0.x, v0.y), fmaxf(v0.z, v0.w)));
        mx = fmaxf(mx, fmaxf(fmaxf(v1.x, v1.y), fmaxf(v1.z, v1.w)));

        #pragma unroll
        for (int off = 16; off > 0; off >>= 1) {
            mn = fminf(mn, __shfl_xor_sync(0xffffffffu, mn, off));
            mx = fmaxf(mx, __shfl_xor_sync(0xffffffffu, mx, off));
        }
        if ((tid & 31) == 0) { red[tid >> 5] = mn; red[8 + (tid >> 5)] = mx; }
        __syncthreads();
        if (tid == 0) {
            float m1 = red[0], m2 = red[8];
            #pragma unroll
            for (int w = 1; w < 8; w++) {
                m1 = fminf(m1, red[w]);
                m2 = fmaxf(m2, red[8 + w]);
            }
            float scale = fmaxf(__fdiv_rn(m2 - m1, 255.0f), 1.1920929e-07f);
            float zpf = -128.0f - rintf(__fdiv_rn(m1, scale));
            zpf = fminf(fmaxf(zpf, -128.0f), 127.0f);
            red[16] = __frcp_rn(scale);   // per-element uses reciprocal-mul
            red[17] = zpf;
            g_xscale[row] = scale;
        }
        __syncthreads();
        const float rs  = red[16];
        const float zpf = red[17];

        // q = clip(rint(x/s) + zp) - zp : integer in [-255,255], exact in fp16
        auto qd = [&](float xv) -> float {
            float q = rintf(xv * rs) + zpf;
            q = fminf(fmaxf(q, -128.0f), 127.0f);
            return q - zpf;
        };

        __half2* xq2 = (__half2*)(g_xq + (size_t)row * DIN);
        xq2[2 * tid]             = __floats2half2_rn(qd(v0.x), qd(v0.y));
        xq2[2 * tid + 1]         = __floats2half2_rn(qd(v0.z), qd(v0.w));
        xq2[2 * (tid + 256)]     = __floats2half2_rn(qd(v1.x), qd(v1.y));
        xq2[2 * (tid + 256) + 1] = __floats2half2_rn(qd(v1.z), qd(v1.w));
    } else {
        // ---- grouped-int4 dequant of W into fp16 ----
        const int idx = (blockIdx.x - MROWS) * 256 + tid;   // one int4 vec
        const int4 w4 = ((const int4*)wi)[idx];
        const int base = idx << 2;
        const int o = base >> 11;                 // / DIN
        const int g = (base & (DIN - 1)) >> 5;    // group of 32
        const float s = ws[o * GROUPS + g];
        const float z = wz[o * GROUPS + g];
        __half2 h01 = __floats2half2_rn(((float)w4.x - z) * s, ((float)w4.y - z) * s);
        __half2 h23 = __floats2half2_rn(((float)w4.z - z) * s, ((float)w4.w - z) * s);
        __half2* dst = (__half2*)(g_wh + base);
        dst[0] = h01;
        dst[1] = h23;
    }
}

// ============================================================================
// Kernel 2: fp16 mma.sync GEMM (NT), CTA 128x128, warp tile 32x64, BK=64,
// 3-stage cp.async pipeline (prefetch distance 2), one barrier per iter,
// 2 CTAs/SM, register-double-buffered fragments (ldsm ka+1 behind MMAs of ka).
//   out[m, n] = g_xscale[m] * sum_k g_xq[m,k] * g_wh[n,k]
//
// SMEM rows: 64 fp16 data + 8 fp16 pad = 144B stride (conflict-free ldmatrix;
// 16B-aligned cp.async chunks; 4-wavefront-optimal stores).
// ============================================================================
static constexpr int BM = 128;
static constexpr int BN = 128;
static constexpr int BK = 64;
static constexpr int KITERS = DIN / BK;            // 32
static constexpr int SROWB = 144;                  // bytes per smem row
static constexpr int TILE_B = 128 * SROWB;         // 18432 per operand
static constexpr int STAGE_B = 2 * TILE_B;         // 36864 (A + B)
static constexpr int NSTAGES = 3;
static constexpr int GEMM_SMEM = NSTAGES * STAGE_B;  // 110592; x2 CTAs = 221KB

__global__ void __launch_bounds__(256, 2)
qgemm_kernel(float* __restrict__ out) {
    extern __shared__ char sm[];
    const uint32_t sbase = smem_to_u32(sm);
    const int tid  = threadIdx.x;
    const int lane = tid & 31;
    const int wid  = tid >> 5;
    const int warp_m = wid & 3;    // 4 m-tiles of 32 rows
    const int warp_n = wid >> 2;   // 2 n-tiles of 64 cols
    const int n0 = blockIdx.x * BN;
    const int m0 = blockIdx.y * BM;

    const __half* ga = g_xq + (size_t)m0 * DIN;
    const __half* gb = g_wh + (size_t)n0 * DIN;

    auto load_stage = [&](int s, int k0) {
        const uint32_t abase = sbase + (uint32_t)s * STAGE_B;
        const uint32_t bbase = abase + (uint32_t)TILE_B;
        #pragma unroll
        for (int it = 0; it < 4; it++) {
            int c = tid + it * 256;          // 0..1023, one 16B chunk each
            int r = c >> 3;                  // row 0..127
            int colh = (c & 7) * 8;          // column in halves
            uint32_t soff = (uint32_t)(r * SROWB + colh * 2);
            cp_async16(abase + soff, ga + (size_t)r * DIN + k0 + colh);
            cp_async16(bbase + soff, gb + (size_t)r * DIN + k0 + colh);
        }
        asm volatile("cp.async.commit_group;" ::: "memory");
    };

    float acc[2][8][4];
    #pragma unroll
    for (int mi = 0; mi < 2; mi++)
        #pragma unroll
        for (int p = 0; p < 8; p++)
            #pragma unroll
            for (int j = 0; j < 4; j++)
                acc[mi][p][j] = 0.0f;

    load_stage(0, 0);
    load_stage(1, BK);

    // ldmatrix lane addressing: lanes 0-15 -> rows, lanes 16-31 -> +16B in k
    const uint32_t lrow = (uint32_t)(lane & 15);
    const uint32_t lkof = (uint32_t)((lane >> 4) * 16);   // bytes

    int sc = 0;
    for (int i = 0; i < KITERS; i++) {
        if (i + 2 < KITERS) cp_wait<1>(); else cp_wait<0>();
        __syncthreads();
        if (i + 2 < KITERS) {
            int sl = sc + 2; if (sl >= NSTAGES) sl -= NSTAGES;
            load_stage(sl, (i + 2) * BK);
        }

        const uint32_t abase = sbase + (uint32_t)sc * STAGE_B;
        const uint32_t bbase = abase + (uint32_t)TILE_B;
        const uint32_t arow0 = abase + (uint32_t)(warp_m * 32 + lrow) * SROWB + lkof;
        const uint32_t brow0 = bbase + (uint32_t)(warp_n * 64 + lrow) * SROWB + lkof;

        // Double-buffered fragments: load ka+1 while MMAs of ka execute.
        uint32_t a[2][2][4];
        uint32_t bq[2][4][4];

        // prime ka = 0 (exposed; data visibility needed this iter's barrier)
        ldsm_x4(a[0][0], arow0);
        ldsm_x4(a[0][1], arow0 + 16u * SROWB);
        #pragma unroll
        for (int t = 0; t < 4; t++)
            ldsm_x4(bq[0][t], brow0 + (uint32_t)(t * 16) * SROWB);

        #pragma unroll
        for (int ka = 0; ka < 4; ka++) {
            const int cur = ka & 1;
            const int nxt = cur ^ 1;
            if (ka < 3) {
                const uint32_t kb2 = (uint32_t)((ka + 1) * 32);
                ldsm_x4(a[nxt][0], arow0 + kb2);
                ldsm_x4(a[nxt][1], arow0 + 16u * SROWB + kb2);
                #pragma unroll
                for (int t = 0; t < 4; t++)
                    ldsm_x4(bq[nxt][t], brow0 + (uint32_t)(t * 16) * SROWB + kb2);
            }
            #pragma unroll
            for (int mi = 0; mi < 2; mi++) {
                #pragma unroll
                for (int t = 0; t < 4; t++) {
                    // x4 B load t covers n-atoms 2t (regs 0,2) and 2t+1 (1,3)
                    mma16816(acc[mi][2 * t],     a[cur][mi], bq[cur][t][0], bq[cur][t][2]);
                    mma16816(acc[mi][2 * t + 1], a[cur][mi], bq[cur][t][1], bq[cur][t][3]);
                }
            }
        }
        sc++; if (sc == NSTAGES) sc = 0;
    }

    // Epilogue: scale by per-token scale, store fp32.
    const int qrow = lane >> 2;          // 0..7
    const int qcol = (lane & 3) * 2;     // 0,2,4,6
    #pragma unroll
    for (int mi = 0; mi < 2; mi++) {
        const int mrow0 = m0 + warp_m * 32 + mi * 16 + qrow;
        const float sc0 = g_xscale[mrow0];
        const float sc1 = g_xscale[mrow0 + 8];
        float* o0 = out + (size_t)mrow0 * DOUT + n0 + warp_n * 64 + qcol;
        float* o1 = o0 + (size_t)8 * DOUT;
        #pragma unroll
        for (int p = 0; p < 8; p++) {
            *(float2*)(o0 + p * 8) = make_float2(sc0 * acc[mi][p][0],
                                                 sc0 * acc[mi][p][1]);
            *(float2*)(o1 + p * 8) = make_float2(sc1 * acc[mi][p][2],
                                                 sc1 * acc[mi][p][3]);
        }
    }
}

// ============================================================================
// Launch
// ============================================================================
extern "C" void kernel_launch(void* const* d_in, const int* in_sizes, int n_in,
                              void* d_out, int out_size) {
    (void)in_sizes; (void)n_in; (void)out_size;
    const float* x  = (const float*)d_in[0];
    const int*   wi = (const int*)d_in[1];
    const float* ws = (const float*)d_in[2];
    const float* wz = (const float*)d_in[3];
    float* out = (float*)d_out;

    cudaFuncSetAttribute(qgemm_kernel,
                         cudaFuncAttributeMaxDynamicSharedMemorySize, GEMM_SMEM);

    prep_kernel<<<MROWS + (DOUT * DIN) / 1024, 256>>>(x, wi, ws, wz);
    qgemm_kernel<<<dim3(DOUT / BN, MROWS / BM), 256, GEMM_SMEM>>>(out);
}